// round 9
// baseline (speedup 1.0000x reference)
#include <cuda_runtime.h>
#include <cuda_bf16.h>
#include <math.h>

#define NROWS 16384
#define HDIM  2048
#define HN    1024   // hidden of both MLPs

// ---------------- scratch (static device allocations only) ----------------
__device__ __nv_bfloat16 g_xb[(size_t)NROWS * HDIM];   // 64 MB bf16 copy of x
__device__ __nv_bfloat16 g_w1b[(size_t)HDIM * HN];     // 4 MB bf16 copy of W_e1
__device__ float g_score_parts[(size_t)NROWS * 16];    // per-row, per-128col score partials
__device__ float g_ew[NROWS];                          // exp(importance) masked by event
__device__ float g_blockZ[64];
__device__ float g_blockCnt[64];
__device__ float g_cons_parts[64 * HDIM];
__device__ float g_c[HDIM];                            // consolidated
__device__ float g_r1_parts[16 * HN];
__device__ float g_h1[HN];
__device__ float g_add[HDIM];

// ---------------- 0) fp32 -> bf16 conversion of x and W_e1 ----------------
__global__ void k_convert(const float* __restrict__ x, const float* __restrict__ w1) {
    long i = (long)blockIdx.x * 256 + threadIdx.x;        // one float4 per thread
    const long NX4 = (long)NROWS * HDIM / 4;
    float4 v;
    __nv_bfloat16* dst;
    if (i < NX4) { v = ((const float4*)x)[i];  dst = g_xb + i * 4; }
    else { long j = i - NX4; v = ((const float4*)w1)[j]; dst = g_w1b + j * 4; }
    __nv_bfloat16 h[4];
    h[0] = __float2bfloat16(v.x); h[1] = __float2bfloat16(v.y);
    h[2] = __float2bfloat16(v.z); h[3] = __float2bfloat16(v.w);
    *reinterpret_cast<uint2*>(dst) = *reinterpret_cast<uint2*>(h);
}

// ---------------- 1) fused detector GEMM + score-GEMV epilogue -------------
// C tile 128x128, K-chunk 32, 8 warps (4 in M x 2 in N), warp tile 32x64.
__global__ __launch_bounds__(256, 2) void k_gemm_score(
    const float* __restrict__ b_e1, const float* __restrict__ w_e2)
{
    __shared__ __nv_bfloat16 As[2][128][40];   // pad 32->40 halves (80B rows)
    __shared__ __nv_bfloat16 Bs[2][32][136];   // pad 128->136 halves (272B rows)
    __shared__ float be1s[128];
    __shared__ float w2s[128];

    const int tid  = threadIdx.x;
    const int lane = tid & 31;
    const int wid  = tid >> 5;
    const int wm   = wid & 3;       // warp row (32 rows each)
    const int wn   = wid >> 2;      // warp col (64 cols each)
    const int m0   = blockIdx.y * 128;
    const int n0   = blockIdx.x * 128;

    if (tid < 128) { be1s[tid] = b_e1[n0 + tid]; w2s[tid] = w_e2[n0 + tid]; }

    float acc[2][8][4];
#pragma unroll
    for (int mi = 0; mi < 2; mi++)
#pragma unroll
        for (int ni = 0; ni < 8; ni++)
#pragma unroll
            for (int d = 0; d < 4; d++) acc[mi][ni][d] = 0.f;

    auto loadTiles = [&](int buf, int kc) {
        int k0 = kc * 32;
#pragma unroll
        for (int i = 0; i < 2; i++) {                 // A: 128x32 bf16 via 512 16B chunks
            int c = tid + i * 256;
            int row = c >> 2, ko = (c & 3) * 8;
            const __nv_bfloat16* g = &g_xb[(size_t)(m0 + row) * HDIM + k0 + ko];
            unsigned s = (unsigned)__cvta_generic_to_shared(&As[buf][row][ko]);
            asm volatile("cp.async.cg.shared.global [%0], [%1], 16;\n" :: "r"(s), "l"(g));
        }
#pragma unroll
        for (int i = 0; i < 2; i++) {                 // B: 32x128 bf16 via 512 16B chunks
            int c = tid + i * 256;
            int kr = c >> 4, no = (c & 15) * 8;
            const __nv_bfloat16* g = &g_w1b[(size_t)(k0 + kr) * HN + n0 + no];
            unsigned s = (unsigned)__cvta_generic_to_shared(&Bs[buf][kr][no]);
            asm volatile("cp.async.ca.shared.global [%0], [%1], 16;\n" :: "r"(s), "l"(g));
        }
    };

    loadTiles(0, 0);
    asm volatile("cp.async.commit_group;\n");
    int buf = 0;
    for (int kc = 0; kc < 64; ++kc) {
        if (kc < 63) {
            loadTiles(buf ^ 1, kc + 1);
            asm volatile("cp.async.commit_group;\n");
            asm volatile("cp.async.wait_group 1;\n");
        } else {
            asm volatile("cp.async.wait_group 0;\n");
        }
        __syncthreads();

#pragma unroll
        for (int ks = 0; ks < 2; ++ks) {
            const int kk = ks * 16;
            unsigned a[2][4];
#pragma unroll
            for (int mi = 0; mi < 2; mi++) {
                unsigned addr = (unsigned)__cvta_generic_to_shared(
                    &As[buf][wm * 32 + mi * 16 + (lane & 15)][kk + ((lane >> 4) << 3)]);
                asm volatile("ldmatrix.sync.aligned.m8n8.x4.shared.b16 {%0,%1,%2,%3}, [%4];"
                    : "=r"(a[mi][0]), "=r"(a[mi][1]), "=r"(a[mi][2]), "=r"(a[mi][3]) : "r"(addr));
            }
            unsigned b[8][2];
#pragma unroll
            for (int ni = 0; ni < 8; ni++) {
                unsigned addr = (unsigned)__cvta_generic_to_shared(
                    &Bs[buf][kk + (lane & 15)][wn * 64 + ni * 8]);
                asm volatile("ldmatrix.sync.aligned.m8n8.x2.trans.shared.b16 {%0,%1}, [%2];"
                    : "=r"(b[ni][0]), "=r"(b[ni][1]) : "r"(addr));
            }
#pragma unroll
            for (int mi = 0; mi < 2; mi++)
#pragma unroll
                for (int ni = 0; ni < 8; ni++)
                    asm volatile(
                        "mma.sync.aligned.m16n8k16.row.col.f32.bf16.bf16.f32 "
                        "{%0,%1,%2,%3}, {%4,%5,%6,%7}, {%8,%9}, {%0,%1,%2,%3};"
                        : "+f"(acc[mi][ni][0]), "+f"(acc[mi][ni][1]),
                          "+f"(acc[mi][ni][2]), "+f"(acc[mi][ni][3])
                        : "r"(a[mi][0]), "r"(a[mi][1]), "r"(a[mi][2]), "r"(a[mi][3]),
                          "r"(b[ni][0]), "r"(b[ni][1]));
        }
        __syncthreads();
        buf ^= 1;
    }

    // Epilogue: hidden = relu(acc + b_e1); partial score = hidden . W_e2 over 128 cols.
    float s4[4] = {0.f, 0.f, 0.f, 0.f};
#pragma unroll
    for (int mi = 0; mi < 2; mi++) {
#pragma unroll
        for (int ni = 0; ni < 8; ni++) {
            int c0 = wn * 64 + ni * 8 + 2 * (lane & 3);
            float w0 = w2s[c0], w1v = w2s[c0 + 1];
            float bb0 = be1s[c0], bb1 = be1s[c0 + 1];
            s4[mi * 2 + 0] += fmaxf(acc[mi][ni][0] + bb0, 0.f) * w0
                            + fmaxf(acc[mi][ni][1] + bb1, 0.f) * w1v;
            s4[mi * 2 + 1] += fmaxf(acc[mi][ni][2] + bb0, 0.f) * w0
                            + fmaxf(acc[mi][ni][3] + bb1, 0.f) * w1v;
        }
    }
#pragma unroll
    for (int j = 0; j < 4; j++) {
        s4[j] += __shfl_xor_sync(0xffffffffu, s4[j], 1);
        s4[j] += __shfl_xor_sync(0xffffffffu, s4[j], 2);
    }
    if ((lane & 3) == 0) {
        int rb = m0 + wm * 32 + (lane >> 2);
        int col = blockIdx.x * 2 + wn;
        g_score_parts[(size_t)(rb +  0) * 16 + col] = s4[0];
        g_score_parts[(size_t)(rb +  8) * 16 + col] = s4[1];
        g_score_parts[(size_t)(rb + 16) * 16 + col] = s4[2];
        g_score_parts[(size_t)(rb + 24) * 16 + col] = s4[3];
    }
}

// ---------------- 2) score finalize: sigmoid/threshold/exp + block sums ----
__global__ void k_scores(const float* __restrict__ b_e2, const float* __restrict__ imp) {
    int tid = threadIdx.x;
    int r = blockIdx.x * 256 + tid;
    const float4* p = (const float4*)(g_score_parts + (size_t)r * 16);
    float s = b_e2[0];
#pragma unroll
    for (int i = 0; i < 4; i++) { float4 v = p[i]; s += (v.x + v.y) + (v.z + v.w); }
    float sig = 1.f / (1.f + expf(-s));
    bool ev = sig > 0.7f;
    float ew = ev ? expf(imp[r]) : 0.f;
    g_ew[r] = ew;
    __shared__ float sZ[256];
    __shared__ float sC[256];
    sZ[tid] = ew; sC[tid] = ev ? 1.f : 0.f;
    __syncthreads();
    for (int o = 128; o > 0; o >>= 1) {
        if (tid < o) { sZ[tid] += sZ[tid + o]; sC[tid] += sC[tid + o]; }
        __syncthreads();
    }
    if (tid == 0) { g_blockZ[blockIdx.x] = sZ[0]; g_blockCnt[blockIdx.x] = sC[0]; }
}

// ---------------- 3) consolidated (unnormalized) partials ------------------
__global__ void k_cons(const float* __restrict__ x) {
    int h = blockIdx.x * 256 + threadIdx.x;    // 8 col-blocks
    int r0 = blockIdx.y * 256;                 // 64 row-splits
    float acc = 0.f;
    for (int r = r0; r < r0 + 256; ++r) {
        float w = g_ew[r];
        if (w != 0.f) acc += w * x[(size_t)r * HDIM + h];   // branch uniform per block
    }
    g_cons_parts[(size_t)blockIdx.y * HDIM + h] = acc;
}

__global__ void k_cons_reduce() {
    int h = blockIdx.x * 1024 + threadIdx.x;   // 2 blocks x 1024
    float Z = 0.f;
#pragma unroll
    for (int i = 0; i < 64; i++) Z += g_blockZ[i];
    float a = 0.f;
#pragma unroll 8
    for (int i = 0; i < 64; i++) a += g_cons_parts[(size_t)i * HDIM + h];
    g_c[h] = (Z > 0.f) ? (a / Z) : 0.f;
}

// ---------------- 4) retrieval MLP -----------------------------------------
__global__ void k_r1(const float* __restrict__ W_r1) {
    int j = blockIdx.x * 256 + threadIdx.x;    // 4 j-blocks
    int k0 = blockIdx.y * 128;                 // 16 k-splits
    float acc = 0.f;
#pragma unroll 8
    for (int k = k0; k < k0 + 128; ++k) acc += g_c[k] * W_r1[(size_t)k * HN + j];
    g_r1_parts[(size_t)blockIdx.y * HN + j] = acc;
}

__global__ void k_r1_reduce(const float* __restrict__ b_r1) {
    int j = threadIdx.x;                       // 1 block x 1024
    float a = b_r1[j];
#pragma unroll
    for (int i = 0; i < 16; i++) a += g_r1_parts[(size_t)i * HN + j];
    g_h1[j] = fmaxf(a, 0.f);
}

__global__ void k_r2(const float* __restrict__ W_r2, const float* __restrict__ b_r2) {
    __shared__ float h1s[HN];
    int tid = threadIdx.x;
    for (int i = tid; i < HN; i += 256) h1s[i] = g_h1[i];
    __syncthreads();
    int h = blockIdx.x * 256 + tid;            // 8 blocks
    float acc = b_r2[h];
#pragma unroll 8
    for (int j = 0; j < HN; ++j) acc += h1s[j] * W_r2[(size_t)j * HDIM + h];
    float cnt = 0.f;
#pragma unroll
    for (int i = 0; i < 64; i++) cnt += g_blockCnt[i];
    g_add[h] = (cnt > 0.f) ? (1.f / (1.f + expf(-acc))) : 0.f;
}

// ---------------- 5) out = x + add[None, :] --------------------------------
__global__ void k_out(const float* __restrict__ x, float* __restrict__ out) {
    size_t i = (size_t)blockIdx.x * 256 + threadIdx.x;   // one float4 per thread
    float4 v = ((const float4*)x)[i];
    float4 a = ((const float4*)g_add)[i & 511];          // HDIM/4 = 512
    v.x += a.x; v.y += a.y; v.z += a.z; v.w += a.w;
    ((float4*)out)[i] = v;
}

// ---------------------------------------------------------------------------
extern "C" void kernel_launch(void* const* d_in, const int* in_sizes, int n_in,
                              void* d_out, int out_size) {
    const float* x    = (const float*)d_in[0];
    const float* imp  = (const float*)d_in[1];
    const float* W_e1 = (const float*)d_in[2];
    const float* b_e1 = (const float*)d_in[3];
    const float* W_e2 = (const float*)d_in[4];
    const float* b_e2 = (const float*)d_in[5];
    const float* W_r1 = (const float*)d_in[6];
    const float* b_r1 = (const float*)d_in[7];
    const float* W_r2 = (const float*)d_in[8];
    const float* b_r2 = (const float*)d_in[9];
    float* out = (float*)d_out;

    // 0) convert x and W_e1 to bf16   ((16384*2048 + 2048*1024)/4 = 8,912,896 float4)
    k_convert<<<34816, 256>>>(x, W_e1);
    // 1) fused detector GEMM + score epilogue
    k_gemm_score<<<dim3(8, 128), 256>>>(b_e1, W_e2);
    // 2) finalize scores, event mask, softmax numerators + block sums
    k_scores<<<64, 256>>>(b_e2, imp);
    // 3) weighted row-sum (consolidated memory)
    k_cons<<<dim3(8, 64), 256>>>(x);
    k_cons_reduce<<<2, 1024>>>();
    // 4) retrieval MLP
    k_r1<<<dim3(4, 16), 256>>>(W_r1);
    k_r1_reduce<<<1, 1024>>>(b_r1);
    k_r2<<<8, 256>>>(W_r2, b_r2);
    // 5) broadcast add
    k_out<<<32768, 256>>>(x, out);
}

// round 12
// speedup vs baseline: 1.0329x; 1.0329x over previous
#include <cuda_runtime.h>
#include <cuda_bf16.h>
#include <math.h>
#include <stdint.h>

#define NROWS 16384
#define HDIM  2048
#define HN    1024

// ---------------- scratch (static device allocations only) ----------------
__device__ __nv_bfloat16 g_xb[(size_t)NROWS * HDIM];   // 64 MB bf16 copy of x
__device__ __nv_bfloat16 g_w1b[(size_t)HDIM * HN];     // 4 MB bf16 W_e1 [K,N]
__device__ float g_score_parts[(size_t)NROWS * 16];    // per-row, per-128col partials
__device__ float g_ew[NROWS];
__device__ float g_blockZ[64];
__device__ float g_blockCnt[64];
__device__ float g_cons_parts[128 * HDIM];
__device__ float g_c[HDIM];
__device__ float g_r1_parts[16 * HN];
__device__ float g_h1[HN];
__device__ float g_add[HDIM];

// ---------------- 0) fp32 -> bf16 conversion of x and W_e1 ----------------
__global__ void k_convert(const float* __restrict__ x, const float* __restrict__ w1) {
    long i = (long)blockIdx.x * 256 + threadIdx.x;        // one float4 per thread
    const long NX4 = (long)NROWS * HDIM / 4;
    float4 v;
    __nv_bfloat16* dst;
    if (i < NX4) { v = ((const float4*)x)[i];  dst = g_xb + i * 4; }
    else { long j = i - NX4; v = ((const float4*)w1)[j]; dst = g_w1b + j * 4; }
    __nv_bfloat16 h[4];
    h[0] = __float2bfloat16(v.x); h[1] = __float2bfloat16(v.y);
    h[2] = __float2bfloat16(v.z); h[3] = __float2bfloat16(v.w);
    *reinterpret_cast<uint2*>(dst) = *reinterpret_cast<uint2*>(h);
}

// ---------------- 1) fused detector GEMM + score-GEMV epilogue -------------
// C tile 128x128, K-chunk 64, 3-stage cp.async pipeline, 8 warps (4m x 2n),
// warp tile 32x64.  Dynamic SMEM:
//   As: 3 stages x 128 rows x 72 halves  (pad 64->72) = 55296 B
//   Bs: 3 stages x 64 rows x 136 halves  (pad 128->136) = 52224 B
//   be1s/w2s: 128 floats each
#define AS_STAGE 9216          // halves per A stage (128*72)
#define AS_ROW   72
#define BS_STAGE 8704          // halves per B stage (64*136)
#define BS_ROW   136
#define OFF_BS   55296         // bytes
#define OFF_BE1  107520
#define OFF_W2   108032
#define GEMM_SMEM 108544

__global__ __launch_bounds__(256, 2) void k_gemm_score(
    const float* __restrict__ b_e1, const float* __restrict__ w_e2)
{
    extern __shared__ char smem[];
    __nv_bfloat16* As = (__nv_bfloat16*)smem;
    __nv_bfloat16* Bs = (__nv_bfloat16*)(smem + OFF_BS);
    float* be1s = (float*)(smem + OFF_BE1);
    float* w2s  = (float*)(smem + OFF_W2);

    const int tid  = threadIdx.x;
    const int lane = tid & 31;
    const int wid  = tid >> 5;
    const int wm   = wid & 3;       // warp row (32 rows each)
    const int wn   = wid >> 2;      // warp col (64 cols each)
    const int m0   = blockIdx.y * 128;
    const int n0   = blockIdx.x * 128;

    if (tid < 128) { be1s[tid] = b_e1[n0 + tid]; w2s[tid] = w_e2[n0 + tid]; }

    float acc[2][8][4];
#pragma unroll
    for (int mi = 0; mi < 2; mi++)
#pragma unroll
        for (int ni = 0; ni < 8; ni++)
#pragma unroll
            for (int d = 0; d < 4; d++) acc[mi][ni][d] = 0.f;

    auto loadStage = [&](int s, int kc) {
        int k0 = kc * 64;
#pragma unroll
        for (int i = 0; i < 4; i++) {                 // A: 128 rows x 8 16B-chunks
            int c = tid + i * 256;
            int row = c >> 3, ko = (c & 7) * 8;
            const __nv_bfloat16* g = &g_xb[(size_t)(m0 + row) * HDIM + k0 + ko];
            unsigned d = (unsigned)__cvta_generic_to_shared(&As[s * AS_STAGE + row * AS_ROW + ko]);
            asm volatile("cp.async.cg.shared.global [%0], [%1], 16;\n" :: "r"(d), "l"(g));
        }
#pragma unroll
        for (int i = 0; i < 4; i++) {                 // B: 64 rows x 16 16B-chunks
            int c = tid + i * 256;
            int kr = c >> 4, no = (c & 15) * 8;
            const __nv_bfloat16* g = &g_w1b[(size_t)(k0 + kr) * HN + n0 + no];
            unsigned d = (unsigned)__cvta_generic_to_shared(&Bs[s * BS_STAGE + kr * BS_ROW + no]);
            asm volatile("cp.async.ca.shared.global [%0], [%1], 16;\n" :: "r"(d), "l"(g));
        }
    };

    loadStage(0, 0);
    asm volatile("cp.async.commit_group;\n");
    loadStage(1, 1);
    asm volatile("cp.async.commit_group;\n");

    for (int c = 0; c < 32; ++c) {
        const int buf = c % 3;
        if (c + 2 < 32) loadStage((c + 2) % 3, c + 2);
        asm volatile("cp.async.commit_group;\n");     // (possibly empty group)
        asm volatile("cp.async.wait_group 2;\n");
        __syncthreads();

        const __nv_bfloat16* Ab = As + buf * AS_STAGE;
        const __nv_bfloat16* Bb = Bs + buf * BS_STAGE;
#pragma unroll
        for (int ks = 0; ks < 4; ++ks) {
            const int kk = ks * 16;
            unsigned a[2][4];
#pragma unroll
            for (int mi = 0; mi < 2; mi++) {
                unsigned addr = (unsigned)__cvta_generic_to_shared(
                    &Ab[(wm * 32 + mi * 16 + (lane & 15)) * AS_ROW + kk + ((lane >> 4) << 3)]);
                asm volatile("ldmatrix.sync.aligned.m8n8.x4.shared.b16 {%0,%1,%2,%3}, [%4];"
                    : "=r"(a[mi][0]), "=r"(a[mi][1]), "=r"(a[mi][2]), "=r"(a[mi][3]) : "r"(addr));
            }
            unsigned b[4][4];                          // [nj: 16-col group][4 regs]
#pragma unroll
            for (int nj = 0; nj < 4; nj++) {
                unsigned addr = (unsigned)__cvta_generic_to_shared(
                    &Bb[(kk + (lane & 15)) * BS_ROW + wn * 64 + nj * 16 + ((lane >> 4) << 3)]);
                asm volatile("ldmatrix.sync.aligned.m8n8.x4.trans.shared.b16 {%0,%1,%2,%3}, [%4];"
                    : "=r"(b[nj][0]), "=r"(b[nj][1]), "=r"(b[nj][2]), "=r"(b[nj][3]) : "r"(addr));
            }
#pragma unroll
            for (int mi = 0; mi < 2; mi++)
#pragma unroll
                for (int ni = 0; ni < 8; ni++) {
                    const int nj = ni >> 1, hb = (ni & 1) * 2;
                    asm volatile(
                        "mma.sync.aligned.m16n8k16.row.col.f32.bf16.bf16.f32 "
                        "{%0,%1,%2,%3}, {%4,%5,%6,%7}, {%8,%9}, {%0,%1,%2,%3};"
                        : "+f"(acc[mi][ni][0]), "+f"(acc[mi][ni][1]),
                          "+f"(acc[mi][ni][2]), "+f"(acc[mi][ni][3])
                        : "r"(a[mi][0]), "r"(a[mi][1]), "r"(a[mi][2]), "r"(a[mi][3]),
                          "r"(b[nj][hb]), "r"(b[nj][hb + 1]));
                }
        }
        __syncthreads();
    }

    // Epilogue: hidden = relu(acc + b_e1); partial score = hidden . W_e2 over 128 cols.
    float s4[4] = {0.f, 0.f, 0.f, 0.f};
#pragma unroll
    for (int mi = 0; mi < 2; mi++) {
#pragma unroll
        for (int ni = 0; ni < 8; ni++) {
            int c0 = wn * 64 + ni * 8 + 2 * (lane & 3);
            float w0 = w2s[c0], w1v = w2s[c0 + 1];
            float bb0 = be1s[c0], bb1 = be1s[c0 + 1];
            s4[mi * 2 + 0] += fmaxf(acc[mi][ni][0] + bb0, 0.f) * w0
                            + fmaxf(acc[mi][ni][1] + bb1, 0.f) * w1v;
            s4[mi * 2 + 1] += fmaxf(acc[mi][ni][2] + bb0, 0.f) * w0
                            + fmaxf(acc[mi][ni][3] + bb1, 0.f) * w1v;
        }
    }
#pragma unroll
    for (int j = 0; j < 4; j++) {
        s4[j] += __shfl_xor_sync(0xffffffffu, s4[j], 1);
        s4[j] += __shfl_xor_sync(0xffffffffu, s4[j], 2);
    }
    if ((lane & 3) == 0) {
        int rb = m0 + wm * 32 + (lane >> 2);
        int col = blockIdx.x * 2 + wn;
        g_score_parts[(size_t)(rb +  0) * 16 + col] = s4[0];
        g_score_parts[(size_t)(rb +  8) * 16 + col] = s4[1];
        g_score_parts[(size_t)(rb + 16) * 16 + col] = s4[2];
        g_score_parts[(size_t)(rb + 24) * 16 + col] = s4[3];
    }
}

// ---------------- 2) score finalize: sigmoid/threshold/exp + block sums ----
__global__ void k_scores(const float* __restrict__ b_e2, const float* __restrict__ imp) {
    int tid = threadIdx.x;
    int r = blockIdx.x * 256 + tid;
    const float4* p = (const float4*)(g_score_parts + (size_t)r * 16);
    float s = b_e2[0];
#pragma unroll
    for (int i = 0; i < 4; i++) { float4 v = p[i]; s += (v.x + v.y) + (v.z + v.w); }
    float sig = 1.f / (1.f + expf(-s));
    bool ev = sig > 0.7f;
    float ew = ev ? expf(imp[r]) : 0.f;
    g_ew[r] = ew;
    __shared__ float sZ[256];
    __shared__ float sC[256];
    sZ[tid] = ew; sC[tid] = ev ? 1.f : 0.f;
    __syncthreads();
    for (int o = 128; o > 0; o >>= 1) {
        if (tid < o) { sZ[tid] += sZ[tid + o]; sC[tid] += sC[tid + o]; }
        __syncthreads();
    }
    if (tid == 0) { g_blockZ[blockIdx.x] = sZ[0]; g_blockCnt[blockIdx.x] = sC[0]; }
}

// ---------------- 3) consolidated partials (bf16 x, halves bytes) ----------
__global__ __launch_bounds__(256) void k_cons() {
    int tid = threadIdx.x;
    int r0 = blockIdx.x * 128;                 // 128 row-splits
    __shared__ float ws[128];
    if (tid < 128) ws[tid] = g_ew[r0 + tid];
    __syncthreads();
    float acc[8] = {0.f, 0.f, 0.f, 0.f, 0.f, 0.f, 0.f, 0.f};
    for (int rr = 0; rr < 128; rr++) {
        float w = ws[rr];
        if (w == 0.f) continue;                // uniform across block
        uint4 p = *reinterpret_cast<const uint4*>(g_xb + (size_t)(r0 + rr) * HDIM + tid * 8);
        const __nv_bfloat162* h = reinterpret_cast<const __nv_bfloat162*>(&p);
#pragma unroll
        for (int q = 0; q < 4; q++) {
            float2 f = __bfloat1622float2(h[q]);
            acc[q * 2 + 0] += w * f.x;
            acc[q * 2 + 1] += w * f.y;
        }
    }
    float* dst = g_cons_parts + (size_t)blockIdx.x * HDIM + tid * 8;
    ((float4*)dst)[0] = make_float4(acc[0], acc[1], acc[2], acc[3]);
    ((float4*)dst)[1] = make_float4(acc[4], acc[5], acc[6], acc[7]);
}

__global__ void k_cons_reduce() {
    int h = blockIdx.x * 1024 + threadIdx.x;   // 2 blocks x 1024
    float Z = 0.f;
#pragma unroll
    for (int i = 0; i < 64; i++) Z += g_blockZ[i];
    float a = 0.f;
#pragma unroll 8
    for (int i = 0; i < 128; i++) a += g_cons_parts[(size_t)i * HDIM + h];
    g_c[h] = (Z > 0.f) ? (a / Z) : 0.f;
}

// ---------------- 4) retrieval MLP -----------------------------------------
__global__ void k_r1(const float* __restrict__ W_r1) {
    int j = blockIdx.x * 256 + threadIdx.x;    // 4 j-blocks
    int k0 = blockIdx.y * 128;                 // 16 k-splits
    float acc = 0.f;
#pragma unroll 8
    for (int k = k0; k < k0 + 128; ++k) acc += g_c[k] * W_r1[(size_t)k * HN + j];
    g_r1_parts[(size_t)blockIdx.y * HN + j] = acc;
}

__global__ void k_r1_reduce(const float* __restrict__ b_r1) {
    int j = threadIdx.x;                       // 1 block x 1024
    float a = b_r1[j];
#pragma unroll
    for (int i = 0; i < 16; i++) a += g_r1_parts[(size_t)i * HN + j];
    g_h1[j] = fmaxf(a, 0.f);
}

__global__ void k_r2(const float* __restrict__ W_r2, const float* __restrict__ b_r2) {
    __shared__ float h1s[HN];
    int tid = threadIdx.x;
    for (int i = tid; i < HN; i += 256) h1s[i] = g_h1[i];
    __syncthreads();
    int h = blockIdx.x * 256 + tid;            // 8 blocks
    float acc = b_r2[h];
#pragma unroll 8
    for (int j = 0; j < HN; ++j) acc += h1s[j] * W_r2[(size_t)j * HDIM + h];
    float cnt = 0.f;
#pragma unroll
    for (int i = 0; i < 64; i++) cnt += g_blockCnt[i];
    g_add[h] = (cnt > 0.f) ? (1.f / (1.f + expf(-acc))) : 0.f;
}

// ---------------- 5) out = x + add[None, :] --------------------------------
__global__ void k_out(const float* __restrict__ x, float* __restrict__ out) {
    size_t i = (size_t)blockIdx.x * 256 + threadIdx.x;   // one float4 per thread
    float4 v = ((const float4*)x)[i];
    float4 a = ((const float4*)g_add)[i & 511];          // HDIM/4 = 512
    v.x += a.x; v.y += a.y; v.z += a.z; v.w += a.w;
    ((float4*)out)[i] = v;
}

// ---------------------------------------------------------------------------
extern "C" void kernel_launch(void* const* d_in, const int* in_sizes, int n_in,
                              void* d_out, int out_size) {
    const float* x    = (const float*)d_in[0];
    const float* imp  = (const float*)d_in[1];
    const float* W_e1 = (const float*)d_in[2];
    const float* b_e1 = (const float*)d_in[3];
    const float* W_e2 = (const float*)d_in[4];
    const float* b_e2 = (const float*)d_in[5];
    const float* W_r1 = (const float*)d_in[6];
    const float* b_r1 = (const float*)d_in[7];
    const float* W_r2 = (const float*)d_in[8];
    const float* b_r2 = (const float*)d_in[9];
    float* out = (float*)d_out;

    cudaFuncSetAttribute(k_gemm_score, cudaFuncAttributeMaxDynamicSharedMemorySize, GEMM_SMEM);

    // 0) convert x and W_e1 to bf16   ((16384*2048 + 2048*1024)/4 = 8,912,896 float4)
    k_convert<<<34816, 256>>>(x, W_e1);
    // 1) fused detector GEMM + score epilogue
    k_gemm_score<<<dim3(8, 128), 256, GEMM_SMEM>>>(b_e1, W_e2);
    // 2) finalize scores, event mask, softmax numerators + block sums
    k_scores<<<64, 256>>>(b_e2, imp);
    // 3) weighted row-sum (consolidated memory, bf16 reads)
    k_cons<<<128, 256>>>();
    k_cons_reduce<<<2, 1024>>>();
    // 4) retrieval MLP
    k_r1<<<dim3(4, 16), 256>>>(W_r1);
    k_r1_reduce<<<1, 1024>>>(b_r1);
    k_r2<<<8, 256>>>(W_r2, b_r2);
    // 5) broadcast add
    k_out<<<32768, 256>>>(x, out);
}

// round 13
// speedup vs baseline: 1.0460x; 1.0127x over previous
#include <cuda_runtime.h>
#include <cuda_bf16.h>
#include <cuda_fp8.h>
#include <math.h>
#include <stdint.h>

#define NROWS 16384
#define HDIM  2048
#define HN    1024

// ---------------- scratch (static device allocations only) ----------------
__device__ unsigned char g_x8[(size_t)NROWS * HDIM];   // 32 MB e4m3 copy of x
__device__ unsigned char g_w8T[(size_t)HN * HDIM];     // 2 MB e4m3 (16*W_e1)^T [N,K]
__device__ float g_score_parts[(size_t)NROWS * 16];    // per-row, per-128col partials
__device__ float g_ew[NROWS];
__device__ float g_blockZ[64];
__device__ float g_blockCnt[64];
__device__ float g_cons_parts[256 * HDIM];
__device__ float g_c[HDIM];
__device__ float g_r1_parts[16 * HN];
__device__ float g_h1[HN];
__device__ float g_add[HDIM];

// ---------------- 0a) x fp32 -> e4m3 ---------------------------------------
__global__ void k_convert_x8(const float* __restrict__ x) {
    size_t i = (size_t)blockIdx.x * 256 + threadIdx.x;   // one float4 -> 4 bytes
    float4 v = ((const float4*)x)[i];
    unsigned lo = __nv_cvt_float2_to_fp8x2(make_float2(v.x, v.y), __NV_SATFINITE, __NV_E4M3);
    unsigned hi = __nv_cvt_float2_to_fp8x2(make_float2(v.z, v.w), __NV_SATFINITE, __NV_E4M3);
    ((unsigned*)g_x8)[i] = lo | (hi << 16);
}

// ---------------- 0b) W_e1 [K,N] fp32 -> (16*W)^T [N,K] e4m3 ---------------
__global__ void k_transpose_w8(const float* __restrict__ w1) {
    __shared__ float t[32][33];
    int n0 = blockIdx.x * 32, k0 = blockIdx.y * 32;
    int tx = threadIdx.x, ty = threadIdx.y;   // 32 x 8
#pragma unroll
    for (int i = 0; i < 4; i++)
        t[ty + i * 8][tx] = w1[(size_t)(k0 + ty + i * 8) * HN + n0 + tx];
    __syncthreads();
#pragma unroll
    for (int i = 0; i < 4; i++) {
        float v = 16.0f * t[tx][ty + i * 8];
        g_w8T[(size_t)(n0 + ty + i * 8) * HDIM + k0 + tx] =
            (unsigned char)__nv_cvt_float_to_fp8(v, __NV_SATFINITE, __NV_E4M3);
    }
}

// ---------------- 1) FP8 detector GEMM + fused score epilogue --------------
// C tile 128x128, K-chunk 64 (2 x k32 mma), 4-stage cp.async pipeline,
// 8 warps (4m x 2n), warp tile 32x64.  SMEM rows padded 64B -> 80B
// (conflict-free for 16B/lane ldmatrix: banks 0,20,8,28,16,4,24,12).
#define AROW 80
#define STG_A 10240            // 128*80
#define STG_B 10240
#define STG   20480
#define OFF_BE1 81920
#define OFF_W2  82432
#define GEMM_SMEM 82944

__global__ __launch_bounds__(256, 2) void k_gemm_score(
    const float* __restrict__ b_e1, const float* __restrict__ w_e2)
{
    extern __shared__ char smem[];
    unsigned char* As = (unsigned char*)smem;
    float* be1s = (float*)(smem + OFF_BE1);
    float* w2s  = (float*)(smem + OFF_W2);

    const int tid  = threadIdx.x;
    const int lane = tid & 31;
    const int wid  = tid >> 5;
    const int wm   = wid & 3;       // warp row (32 rows each)
    const int wn   = wid >> 2;      // warp col (64 cols each)
    const int m0   = blockIdx.y * 128;
    const int n0   = blockIdx.x * 128;

    if (tid < 128) { be1s[tid] = b_e1[n0 + tid]; w2s[tid] = w_e2[n0 + tid]; }

    float acc[2][8][4];
#pragma unroll
    for (int mi = 0; mi < 2; mi++)
#pragma unroll
        for (int ni = 0; ni < 8; ni++)
#pragma unroll
            for (int d = 0; d < 4; d++) acc[mi][ni][d] = 0.f;

    auto loadStage = [&](int s, int kc) {
        int k0 = kc * 64;
        {   // A: 128 rows x 4 16B-chunks, 2 per thread
#pragma unroll
            for (int i = 0; i < 2; i++) {
                int c = tid + i * 256;
                int row = c >> 2, ch = (c & 3) * 16;
                const unsigned char* g = &g_x8[(size_t)(m0 + row) * HDIM + k0 + ch];
                unsigned d = (unsigned)__cvta_generic_to_shared(&As[s * STG + row * AROW + ch]);
                asm volatile("cp.async.cg.shared.global [%0], [%1], 16;\n" :: "r"(d), "l"(g));
            }
        }
        {   // B: 128 n-rows x 4 16B-chunks, 2 per thread
#pragma unroll
            for (int i = 0; i < 2; i++) {
                int c = tid + i * 256;
                int row = c >> 2, ch = (c & 3) * 16;
                const unsigned char* g = &g_w8T[(size_t)(n0 + row) * HDIM + k0 + ch];
                unsigned d = (unsigned)__cvta_generic_to_shared(
                    &As[s * STG + STG_A + row * AROW + ch]);
                asm volatile("cp.async.ca.shared.global [%0], [%1], 16;\n" :: "r"(d), "l"(g));
            }
        }
    };

    loadStage(0, 0); asm volatile("cp.async.commit_group;\n");
    loadStage(1, 1); asm volatile("cp.async.commit_group;\n");
    loadStage(2, 2); asm volatile("cp.async.commit_group;\n");

    for (int c = 0; c < 32; ++c) {
        const int buf = c & 3;
        if (c + 3 < 32) loadStage((c + 3) & 3, c + 3);
        asm volatile("cp.async.commit_group;\n");     // possibly empty group
        asm volatile("cp.async.wait_group 3;\n");
        __syncthreads();

        const unsigned char* Ab = As + buf * STG;
        const unsigned char* Bb = Ab + STG_A;
#pragma unroll
        for (int ks = 0; ks < 2; ++ks) {
            const int kk = ks * 32;                   // byte offset of this k32
            unsigned a[2][4];
#pragma unroll
            for (int mi = 0; mi < 2; mi++) {
                unsigned addr = (unsigned)__cvta_generic_to_shared(
                    &Ab[(wm * 32 + mi * 16 + (lane & 15)) * AROW + kk + ((lane >> 4) << 4)]);
                asm volatile("ldmatrix.sync.aligned.m8n8.x4.shared.b16 {%0,%1,%2,%3}, [%4];"
                    : "=r"(a[mi][0]), "=r"(a[mi][1]), "=r"(a[mi][2]), "=r"(a[mi][3]) : "r"(addr));
            }
            unsigned b[4][4];                          // nq: 16-n-row group
#pragma unroll
            for (int nq = 0; nq < 4; nq++) {
                unsigned addr = (unsigned)__cvta_generic_to_shared(
                    &Bb[(wn * 64 + nq * 16 + (lane & 15)) * AROW + kk + ((lane >> 4) << 4)]);
                asm volatile("ldmatrix.sync.aligned.m8n8.x4.shared.b16 {%0,%1,%2,%3}, [%4];"
                    : "=r"(b[nq][0]), "=r"(b[nq][1]), "=r"(b[nq][2]), "=r"(b[nq][3]) : "r"(addr));
            }
#pragma unroll
            for (int mi = 0; mi < 2; mi++)
#pragma unroll
                for (int ni = 0; ni < 8; ni++) {
                    const int nq = ni >> 1, h = ni & 1;
                    asm volatile(
                        "mma.sync.aligned.m16n8k32.row.col.f32.e4m3.e4m3.f32 "
                        "{%0,%1,%2,%3}, {%4,%5,%6,%7}, {%8,%9}, {%0,%1,%2,%3};"
                        : "+f"(acc[mi][ni][0]), "+f"(acc[mi][ni][1]),
                          "+f"(acc[mi][ni][2]), "+f"(acc[mi][ni][3])
                        : "r"(a[mi][0]), "r"(a[mi][1]), "r"(a[mi][2]), "r"(a[mi][3]),
                          "r"(b[nq][h]), "r"(b[nq][2 + h]));
                }
        }
        __syncthreads();
    }

    // Epilogue: hidden = relu(acc/16 + b_e1); partial score = hidden . W_e2.
    const float SC = 0.0625f;   // undo the x16 weight scale
    float s4[4] = {0.f, 0.f, 0.f, 0.f};
#pragma unroll
    for (int mi = 0; mi < 2; mi++) {
#pragma unroll
        for (int ni = 0; ni < 8; ni++) {
            int c0 = wn * 64 + ni * 8 + 2 * (lane & 3);
            float w0 = w2s[c0], w1v = w2s[c0 + 1];
            float bb0 = be1s[c0], bb1 = be1s[c0 + 1];
            s4[mi * 2 + 0] += fmaxf(acc[mi][ni][0] * SC + bb0, 0.f) * w0
                            + fmaxf(acc[mi][ni][1] * SC + bb1, 0.f) * w1v;
            s4[mi * 2 + 1] += fmaxf(acc[mi][ni][2] * SC + bb0, 0.f) * w0
                            + fmaxf(acc[mi][ni][3] * SC + bb1, 0.f) * w1v;
        }
    }
#pragma unroll
    for (int j = 0; j < 4; j++) {
        s4[j] += __shfl_xor_sync(0xffffffffu, s4[j], 1);
        s4[j] += __shfl_xor_sync(0xffffffffu, s4[j], 2);
    }
    if ((lane & 3) == 0) {
        int rb = m0 + wm * 32 + (lane >> 2);
        int col = blockIdx.x * 2 + wn;
        g_score_parts[(size_t)(rb +  0) * 16 + col] = s4[0];
        g_score_parts[(size_t)(rb +  8) * 16 + col] = s4[1];
        g_score_parts[(size_t)(rb + 16) * 16 + col] = s4[2];
        g_score_parts[(size_t)(rb + 24) * 16 + col] = s4[3];
    }
}

// ---------------- 2) score finalize: sigmoid/threshold/exp + block sums ----
__global__ void k_scores(const float* __restrict__ b_e2, const float* __restrict__ imp) {
    int tid = threadIdx.x;
    int r = blockIdx.x * 256 + tid;
    const float4* p = (const float4*)(g_score_parts + (size_t)r * 16);
    float s = b_e2[0];
#pragma unroll
    for (int i = 0; i < 4; i++) { float4 v = p[i]; s += (v.x + v.y) + (v.z + v.w); }
    float sig = 1.f / (1.f + expf(-s));
    bool ev = sig > 0.7f;
    float ew = ev ? expf(imp[r]) : 0.f;
    g_ew[r] = ew;
    __shared__ float sZ[256];
    __shared__ float sC[256];
    sZ[tid] = ew; sC[tid] = ev ? 1.f : 0.f;
    __syncthreads();
    for (int o = 128; o > 0; o >>= 1) {
        if (tid < o) { sZ[tid] += sZ[tid + o]; sC[tid] += sC[tid + o]; }
        __syncthreads();
    }
    if (tid == 0) { g_blockZ[blockIdx.x] = sZ[0]; g_blockCnt[blockIdx.x] = sC[0]; }
}

// ---------------- 3) consolidated partials (fp32 x, 256 blocks) ------------
__global__ __launch_bounds__(256) void k_cons(const float* __restrict__ x) {
    int tid = threadIdx.x;
    int r0 = blockIdx.x * 64;                  // 256 row-splits of 64 rows
    __shared__ float ws[64];
    if (tid < 64) ws[tid] = g_ew[r0 + tid];
    __syncthreads();
    float acc[8] = {0.f, 0.f, 0.f, 0.f, 0.f, 0.f, 0.f, 0.f};
    for (int rr = 0; rr < 64; rr++) {
        float w = ws[rr];
        if (w == 0.f) continue;                // uniform across block
        const float4* p = (const float4*)(x + (size_t)(r0 + rr) * HDIM + tid * 8);
        float4 v0 = p[0], v1 = p[1];
        acc[0] += w * v0.x; acc[1] += w * v0.y; acc[2] += w * v0.z; acc[3] += w * v0.w;
        acc[4] += w * v1.x; acc[5] += w * v1.y; acc[6] += w * v1.z; acc[7] += w * v1.w;
    }
    float* dst = g_cons_parts + (size_t)blockIdx.x * HDIM + tid * 8;
    ((float4*)dst)[0] = make_float4(acc[0], acc[1], acc[2], acc[3]);
    ((float4*)dst)[1] = make_float4(acc[4], acc[5], acc[6], acc[7]);
}

__global__ void k_cons_reduce() {
    int h = blockIdx.x * 1024 + threadIdx.x;   // 2 blocks x 1024
    float Z = 0.f;
#pragma unroll
    for (int i = 0; i < 64; i++) Z += g_blockZ[i];
    float a = 0.f;
#pragma unroll 8
    for (int i = 0; i < 256; i++) a += g_cons_parts[(size_t)i * HDIM + h];
    g_c[h] = (Z > 0.f) ? (a / Z) : 0.f;
}

// ---------------- 4) retrieval MLP -----------------------------------------
__global__ void k_r1(const float* __restrict__ W_r1) {
    int j = blockIdx.x * 256 + threadIdx.x;    // 4 j-blocks
    int k0 = blockIdx.y * 128;                 // 16 k-splits
    float acc = 0.f;
#pragma unroll 8
    for (int k = k0; k < k0 + 128; ++k) acc += g_c[k] * W_r1[(size_t)k * HN + j];
    g_r1_parts[(size_t)blockIdx.y * HN + j] = acc;
}

__global__ void k_r1_reduce(const float* __restrict__ b_r1) {
    int j = threadIdx.x;                       // 1 block x 1024
    float a = b_r1[j];
#pragma unroll
    for (int i = 0; i < 16; i++) a += g_r1_parts[(size_t)i * HN + j];
    g_h1[j] = fmaxf(a, 0.f);
}

__global__ void k_r2(const float* __restrict__ W_r2, const float* __restrict__ b_r2) {
    __shared__ float h1s[HN];
    int tid = threadIdx.x;
    for (int i = tid; i < HN; i += 256) h1s[i] = g_h1[i];
    __syncthreads();
    int h = blockIdx.x * 256 + tid;            // 8 blocks
    float acc = b_r2[h];
#pragma unroll 8
    for (int j = 0; j < HN; ++j) acc += h1s[j] * W_r2[(size_t)j * HDIM + h];
    float cnt = 0.f;
#pragma unroll
    for (int i = 0; i < 64; i++) cnt += g_blockCnt[i];
    g_add[h] = (cnt > 0.f) ? (1.f / (1.f + expf(-acc))) : 0.f;
}

// ---------------- 5) out = x + add[None, :] --------------------------------
__global__ void k_out(const float* __restrict__ x, float* __restrict__ out) {
    size_t i = (size_t)blockIdx.x * 256 + threadIdx.x;   // one float4 per thread
    float4 v = ((const float4*)x)[i];
    float4 a = ((const float4*)g_add)[i & 511];          // HDIM/4 = 512
    v.x += a.x; v.y += a.y; v.z += a.z; v.w += a.w;
    ((float4*)out)[i] = v;
}

// ---------------------------------------------------------------------------
extern "C" void kernel_launch(void* const* d_in, const int* in_sizes, int n_in,
                              void* d_out, int out_size) {
    const float* x    = (const float*)d_in[0];
    const float* imp  = (const float*)d_in[1];
    const float* W_e1 = (const float*)d_in[2];
    const float* b_e1 = (const float*)d_in[3];
    const float* W_e2 = (const float*)d_in[4];
    const float* b_e2 = (const float*)d_in[5];
    const float* W_r1 = (const float*)d_in[6];
    const float* b_r1 = (const float*)d_in[7];
    const float* W_r2 = (const float*)d_in[8];
    const float* b_r2 = (const float*)d_in[9];
    float* out = (float*)d_out;

    cudaFuncSetAttribute(k_gemm_score, cudaFuncAttributeMaxDynamicSharedMemorySize, GEMM_SMEM);

    // 0) convert x -> e4m3 (8M float4) ; W_e1 -> (16W)^T e4m3
    k_convert_x8<<<32768, 256>>>(x);
    k_transpose_w8<<<dim3(32, 64), dim3(32, 8)>>>(W_e1);
    // 1) fused FP8 detector GEMM + score epilogue
    k_gemm_score<<<dim3(8, 128), 256, GEMM_SMEM>>>(b_e1, W_e2);
    // 2) finalize scores, event mask, softmax numerators + block sums
    k_scores<<<64, 256>>>(b_e2, imp);
    // 3) weighted row-sum (consolidated memory)
    k_cons<<<256, 256>>>(x);
    k_cons_reduce<<<2, 1024>>>();
    // 4) retrieval MLP
    k_r1<<<dim3(4, 16), 256>>>(W_r1);
    k_r1_reduce<<<1, 1024>>>(b_r1);
    k_r2<<<8, 256>>>(W_r2, b_r2);
    // 5) broadcast add
    k_out<<<32768, 256>>>(x, out);
}